// round 6
// baseline (speedup 1.0000x reference)
#include <cuda_runtime.h>

#define NSTEP  25
#define NIN    9
#define NHID   100

__global__ __launch_bounds__(64) void snn_kernel(
    const float* __restrict__ x,
    const float* __restrict__ W1,
    const float* __restrict__ b1,
    const float* __restrict__ W2,
    const float* __restrict__ b2,
    float* __restrict__ out,
    int batch)
{
    // W1 padded to 12 floats/row: [w0..w8, b1, 0, 0] -> 3x LDS.128 per neuron
    __shared__ float4 sW1[NHID * 3];
    __shared__ float2 sW2[NHID];   // packed (W2[0][h], W2[1][h])
    __shared__ float  sb2[2];

    {
        float* sW1f = (float*)sW1;
        for (int h = threadIdx.x; h < NHID; h += blockDim.x) {
#pragma unroll
            for (int i = 0; i < NIN; i++) sW1f[h * 12 + i] = W1[h * NIN + i];
            sW1f[h * 12 + 9]  = b1[h];
            sW1f[h * 12 + 10] = 0.0f;
            sW1f[h * 12 + 11] = 0.0f;
            sW2[h] = make_float2(W2[h], W2[NHID + h]);
        }
        if (threadIdx.x < 2) sb2[threadIdx.x] = b2[threadIdx.x];
    }
    __syncthreads();

    int b = blockIdx.x * blockDim.x + threadIdx.x;
    if (b >= batch) return;

    float xv[NIN];
#pragma unroll
    for (int i = 0; i < NIN; i++) xv[i] = __ldg(&x[(size_t)b * NIN + i]);

    // A[t] packs (cur2_out0[t], cur2_out1[t]) accumulated over all neurons.
    unsigned long long A[NSTEP];
#pragma unroll
    for (int t = 0; t < NSTEP; t++) A[t] = 0ULL;

    // 25 groups of 4 neurons; 4 independent recurrence chains per group.
    for (int g = 0; g < NHID / 4; g++) {
        const int h = g * 4;
        float c[4], cm1[4];
        unsigned long long wpk[4];     // packed (w_out0, w_out1) per neuron
#pragma unroll
        for (int j = 0; j < 4; j++) {
            float4 a0 = sW1[(h + j) * 3 + 0];
            float4 a1 = sW1[(h + j) * 3 + 1];
            float4 a2 = sW1[(h + j) * 3 + 2];
            float cc = a2.y;                   // bias in padded slot 9
            cc = fmaf(xv[0], a0.x, cc); cc = fmaf(xv[1], a0.y, cc);
            cc = fmaf(xv[2], a0.z, cc); cc = fmaf(xv[3], a0.w, cc);
            cc = fmaf(xv[4], a1.x, cc); cc = fmaf(xv[5], a1.y, cc);
            cc = fmaf(xv[6], a1.z, cc); cc = fmaf(xv[7], a1.w, cc);
            cc = fmaf(xv[8], a2.x, cc);
            c[j]   = cc;
            cm1[j] = cc - 1.0f;
            wpk[j] = *(const unsigned long long*)&sW2[h + j];
        }

        // m_0 = 0, first-step reset = 0 -> cr starts at c
        float m[4]  = {0.f, 0.f, 0.f, 0.f};
        float cr[4] = {c[0], c[1], c[2], c[3]};

        // Per neuron-step (4 instr, fma-pipe cost 3 cyc):
        //   m    = beta*m + cr          (FFMA-imm, fma rt1; cr = c - spike_prev)
        //   p    = m > 1                (FSETP, alu)
        //   cr   = p ? c-1 : c          (FSEL pred-as-data, alu)
        //   @p A[t] += (w0,w1)          (predicated packed f32x2 add)
#pragma unroll
        for (int t = 0; t < NSTEP; t++) {
#pragma unroll
            for (int j = 0; j < 4; j++) {
                asm("{\n\t"
                    ".reg .pred p;\n\t"
                    "fma.rn.f32 %0, 0f3F733333, %0, %1;\n\t"
                    "setp.gt.f32 p, %0, 0f3F800000;\n\t"
                    "selp.f32 %1, %3, %4, p;\n\t"
                    "@p add.rn.f32x2 %2, %2, %5;\n\t"
                    "}"
                    : "+f"(m[j]), "+f"(cr[j]), "+l"(A[t])
                    : "f"(cm1[j]), "f"(c[j]), "l"(wpk[j]));
            }
        }
    }

    // Layer-2 LIF recurrence + record mem2 each step
    const float bb0 = sb2[0], bb1 = sb2[1];
    float m20 = 0.0f, m21 = 0.0f;
    float2* outv = (float2*)out;
#pragma unroll
    for (int t = 0; t < NSTEP; t++) {
        float a0f, a1f;
        asm("mov.b64 {%0, %1}, %2;" : "=f"(a0f), "=f"(a1f) : "l"(A[t]));
        float rr0, rr1;                        // reset from PREVIOUS mem2
        asm("set.gt.f32.f32 %0, %1, 0f3F800000;" : "=f"(rr0) : "f"(m20));
        asm("set.gt.f32.f32 %0, %1, 0f3F800000;" : "=f"(rr1) : "f"(m21));
        m20 = fmaf(0.95f, m20, a0f + bb0) - rr0;
        m21 = fmaf(0.95f, m21, a1f + bb1) - rr1;
        outv[(size_t)t * batch + b] = make_float2(m20, m21);
    }
}

extern "C" void kernel_launch(void* const* d_in, const int* in_sizes, int n_in,
                              void* d_out, int out_size)
{
    const float* x  = (const float*)d_in[0];
    const float* W1 = (const float*)d_in[1];
    const float* b1 = (const float*)d_in[2];
    const float* W2 = (const float*)d_in[3];
    const float* b2 = (const float*)d_in[4];
    float* out = (float*)d_out;

    int batch = in_sizes[0] / NIN;
    const int threads = 64;
    int blocks = (batch + threads - 1) / threads;
    snn_kernel<<<blocks, threads>>>(x, W1, b1, W2, b2, out, batch);
}

// round 7
// speedup vs baseline: 1.2509x; 1.2509x over previous
#include <cuda_runtime.h>

#define NSTEP  25
#define NIN    9
#define NHID   100

__global__ __launch_bounds__(64) void snn_kernel(
    const float* __restrict__ x,
    const float* __restrict__ W1,
    const float* __restrict__ b1,
    const float* __restrict__ W2,
    const float* __restrict__ b2,
    float* __restrict__ out,
    int batch)
{
    // W1 padded to 12 floats/row: [w0..w8, b1, 0, 0] -> 3x LDS.128 per neuron
    __shared__ float4 sW1[NHID * 3];
    __shared__ float2 sW2[NHID];   // (W2[0][h], W2[1][h])
    __shared__ float  sb2[2];

    {
        float* sW1f = (float*)sW1;
        for (int h = threadIdx.x; h < NHID; h += blockDim.x) {
#pragma unroll
            for (int i = 0; i < NIN; i++) sW1f[h * 12 + i] = W1[h * NIN + i];
            sW1f[h * 12 + 9]  = b1[h];
            sW1f[h * 12 + 10] = 0.0f;
            sW1f[h * 12 + 11] = 0.0f;
            sW2[h] = make_float2(W2[h], W2[NHID + h]);
        }
        if (threadIdx.x < 2) sb2[threadIdx.x] = b2[threadIdx.x];
    }
    __syncthreads();

    int b = blockIdx.x * blockDim.x + threadIdx.x;
    if (b >= batch) return;

    float xv[NIN];
#pragma unroll
    for (int i = 0; i < NIN; i++) xv[i] = __ldg(&x[(size_t)b * NIN + i]);

    float acc0[NSTEP], acc1[NSTEP];
#pragma unroll
    for (int t = 0; t < NSTEP; t++) { acc0[t] = 0.0f; acc1[t] = 0.0f; }

    // 25 groups of 4 neurons; 4 independent recurrence chains per group.
    for (int g = 0; g < NHID / 4; g++) {
        const int h = g * 4;
        float c[4], cm1[4];
        float2 w[4];
#pragma unroll
        for (int j = 0; j < 4; j++) {
            float4 a0 = sW1[(h + j) * 3 + 0];
            float4 a1 = sW1[(h + j) * 3 + 1];
            float4 a2 = sW1[(h + j) * 3 + 2];
            float cc = a2.y;                   // bias in padded slot 9
            cc = fmaf(xv[0], a0.x, cc); cc = fmaf(xv[1], a0.y, cc);
            cc = fmaf(xv[2], a0.z, cc); cc = fmaf(xv[3], a0.w, cc);
            cc = fmaf(xv[4], a1.x, cc); cc = fmaf(xv[5], a1.y, cc);
            cc = fmaf(xv[6], a1.z, cc); cc = fmaf(xv[7], a1.w, cc);
            cc = fmaf(xv[8], a2.x, cc);
            c[j]   = cc;
            cm1[j] = cc - 1.0f;
            w[j]   = sW2[h + j];
        }

        // m_0 = 0, first-step reset = 0 -> cr starts at c
        float m[4]  = {0.f, 0.f, 0.f, 0.f};
        float cr[4] = {c[0], c[1], c[2], c[3]};

        // Per neuron-step (5 instr; fma 5 cyc, alu 4 cyc):
        //   m  = beta*m + cr        (FFMA-imm, fma rt1; cr = c - spike_prev)
        //   p  = m > 1              (FSETP, alu)
        //   cr = p ? c-1 : c        (FSEL pred-as-data, alu)
        //   @p acc0 += w0           (pred FADD, fma rt2, off-chain)
        //   @p acc1 += w1           (pred FADD, fma rt2, off-chain)
#pragma unroll
        for (int t = 0; t < NSTEP; t++) {
#pragma unroll
            for (int j = 0; j < 4; j++) {
                asm("{\n\t"
                    ".reg .pred p;\n\t"
                    "fma.rn.f32 %0, 0f3F733333, %0, %1;\n\t"
                    "setp.gt.f32 p, %0, 0f3F800000;\n\t"
                    "selp.f32 %1, %4, %5, p;\n\t"
                    "@p add.rn.f32 %2, %2, %6;\n\t"
                    "@p add.rn.f32 %3, %3, %7;\n\t"
                    "}"
                    : "+f"(m[j]), "+f"(cr[j]), "+f"(acc0[t]), "+f"(acc1[t])
                    : "f"(cm1[j]), "f"(c[j]), "f"(w[j].x), "f"(w[j].y));
            }
        }
    }

    // Layer-2 LIF recurrence + record mem2 each step
    const float bb0 = sb2[0], bb1 = sb2[1];
    float m20 = 0.0f, m21 = 0.0f;
    float2* outv = (float2*)out;
#pragma unroll
    for (int t = 0; t < NSTEP; t++) {
        float rr0, rr1;                        // reset from PREVIOUS mem2
        asm("set.gt.f32.f32 %0, %1, 0f3F800000;" : "=f"(rr0) : "f"(m20));
        asm("set.gt.f32.f32 %0, %1, 0f3F800000;" : "=f"(rr1) : "f"(m21));
        m20 = fmaf(0.95f, m20, acc0[t] + bb0) - rr0;
        m21 = fmaf(0.95f, m21, acc1[t] + bb1) - rr1;
        outv[(size_t)t * batch + b] = make_float2(m20, m21);
    }
}

extern "C" void kernel_launch(void* const* d_in, const int* in_sizes, int n_in,
                              void* d_out, int out_size)
{
    const float* x  = (const float*)d_in[0];
    const float* W1 = (const float*)d_in[1];
    const float* b1 = (const float*)d_in[2];
    const float* W2 = (const float*)d_in[3];
    const float* b2 = (const float*)d_in[4];
    float* out = (float*)d_out;

    int batch = in_sizes[0] / NIN;
    const int threads = 64;
    int blocks = (batch + threads - 1) / threads;
    snn_kernel<<<blocks, threads>>>(x, W1, b1, W2, b2, out, batch);
}